// round 2
// baseline (speedup 1.0000x reference)
#include <cuda_runtime.h>

// GIN MessagePassing on GB300 — round 1: fp32 SIMT tiled-GEMM baseline.
//
// Pipeline:
//   K1: h0[b] = adj[b] @ x[b] + (1+eps)*x[b]         (M=4096, N=256, K=4096, batch 8)
//   K2: h1 = relu(h0 @ W1 + b1)                       (M=32768, N=512, K=256)
//   K3: out = h1 @ W2 + b2                            (M=32768, N=256, K=512)
//
// One templated 128x128x16 tile GEMM, 8x8 per-thread microtile, float4 global
// loads with register prefetch, epilogue fused per stage.

#define BM 128
#define BN 128
#define BK 16

// Scratch (alloc-free rule: __device__ globals)
__device__ float g_h0[8u * 4096u * 256u];   // 33.5 MB
__device__ float g_h1[8u * 4096u * 512u];   // 67 MB

template<int EPI>
__global__ __launch_bounds__(256)
void gemm_epi(const float* __restrict__ Ab, const float* __restrict__ Bb,
              float* __restrict__ Cb,
              const float* __restrict__ xres,   // EPI==1: residual input (batched like C)
              const float* __restrict__ epsp,   // EPI==1: eps scalar
              const float* __restrict__ bias,   // EPI==2/3: bias[N]
              int N, int K,
              long long sA, long long sB, long long sC)
{
    __shared__ float As[BK][BM];
    __shared__ float Bs[BK][BN];

    const int bz = blockIdx.z;
    const float* A = Ab + (long long)bz * sA;
    const float* B = Bb + (long long)bz * sB;
    float*       C = Cb + (long long)bz * sC;

    const int tid = threadIdx.x;
    const int tx  = tid & 15;   // 16 col-threads
    const int ty  = tid >> 4;   // 16 row-threads
    const long long rowStart = (long long)blockIdx.y * BM;
    const int       colStart = blockIdx.x * BN;

    const float* Aptr = A + rowStart * K;
    const float* Bptr = B + colStart;

    float acc[8][8];
#pragma unroll
    for (int i = 0; i < 8; i++)
#pragma unroll
        for (int j = 0; j < 8; j++) acc[i][j] = 0.f;

    // ---- global-load index precompute (512 float4 per tile per operand half) ----
    const int aRow0 = tid >> 2;             // 0..63
    const int aRow1 = aRow0 + 64;           // 64..127
    const int aK    = (tid & 3) << 2;       // 0,4,8,12
    const int bK0   = tid >> 5;             // 0..7
    const int bK1   = bK0 + 8;              // 8..15
    const int bC    = (tid & 31) << 2;      // 0..124

    float4 pa0, pa1, pb0, pb1;

    // prefetch tile 0
    pa0 = *(const float4*)(Aptr + (long long)aRow0 * K + aK);
    pa1 = *(const float4*)(Aptr + (long long)aRow1 * K + aK);
    pb0 = *(const float4*)(Bptr + (long long)bK0 * N + bC);
    pb1 = *(const float4*)(Bptr + (long long)bK1 * N + bC);

    const int nTiles = K / BK;
    for (int kt = 0; kt < nTiles; kt++) {
        // stage registers -> smem (A transposed to [k][m])
        As[aK + 0][aRow0] = pa0.x; As[aK + 1][aRow0] = pa0.y;
        As[aK + 2][aRow0] = pa0.z; As[aK + 3][aRow0] = pa0.w;
        As[aK + 0][aRow1] = pa1.x; As[aK + 1][aRow1] = pa1.y;
        As[aK + 2][aRow1] = pa1.z; As[aK + 3][aRow1] = pa1.w;
        *(float4*)&Bs[bK0][bC] = pb0;
        *(float4*)&Bs[bK1][bC] = pb1;
        __syncthreads();

        // prefetch next tile into registers while computing this one
        if (kt + 1 < nTiles) {
            const float* Ap = Aptr + (kt + 1) * BK;
            const float* Bp = Bptr + (long long)(kt + 1) * BK * N;
            pa0 = *(const float4*)(Ap + (long long)aRow0 * K + aK);
            pa1 = *(const float4*)(Ap + (long long)aRow1 * K + aK);
            pb0 = *(const float4*)(Bp + (long long)bK0 * N + bC);
            pb1 = *(const float4*)(Bp + (long long)bK1 * N + bC);
        }

#pragma unroll
        for (int k = 0; k < BK; k++) {
            float4 a0 = *(const float4*)&As[k][ty * 8];
            float4 a1 = *(const float4*)&As[k][ty * 8 + 4];
            float4 b0 = *(const float4*)&Bs[k][tx * 8];
            float4 b1 = *(const float4*)&Bs[k][tx * 8 + 4];
            float ar[8] = {a0.x, a0.y, a0.z, a0.w, a1.x, a1.y, a1.z, a1.w};
            float br[8] = {b0.x, b0.y, b0.z, b0.w, b1.x, b1.y, b1.z, b1.w};
#pragma unroll
            for (int i = 0; i < 8; i++)
#pragma unroll
                for (int j = 0; j < 8; j++)
                    acc[i][j] = fmaf(ar[i], br[j], acc[i][j]);
        }
        __syncthreads();
    }

    // ---- epilogue ----
    float epsv = 0.f;
    if (EPI == 1) epsv = 1.0f + epsp[0];

#pragma unroll
    for (int i = 0; i < 8; i++) {
        const long long row = rowStart + ty * 8 + i;
#pragma unroll
        for (int j4 = 0; j4 < 2; j4++) {
            const int col = colStart + tx * 8 + j4 * 4;
            float4 v = make_float4(acc[i][j4 * 4 + 0], acc[i][j4 * 4 + 1],
                                   acc[i][j4 * 4 + 2], acc[i][j4 * 4 + 3]);
            if (EPI == 1) {
                float4 xv = *(const float4*)(xres + (long long)bz * sC + row * N + col);
                v.x = fmaf(epsv, xv.x, v.x);
                v.y = fmaf(epsv, xv.y, v.y);
                v.z = fmaf(epsv, xv.z, v.z);
                v.w = fmaf(epsv, xv.w, v.w);
            } else if (EPI == 2) {
                v.x = fmaxf(v.x + bias[col + 0], 0.f);
                v.y = fmaxf(v.y + bias[col + 1], 0.f);
                v.z = fmaxf(v.z + bias[col + 2], 0.f);
                v.w = fmaxf(v.w + bias[col + 3], 0.f);
            } else {
                v.x += bias[col + 0];
                v.y += bias[col + 1];
                v.z += bias[col + 2];
                v.w += bias[col + 3];
            }
            *(float4*)(C + row * N + col) = v;
        }
    }
}

extern "C" void kernel_launch(void* const* d_in, const int* in_sizes, int n_in,
                              void* d_out, int out_size)
{
    (void)in_sizes; (void)n_in; (void)out_size;
    const float* x   = (const float*)d_in[0];
    const float* adj = (const float*)d_in[1];
    const float* eps = (const float*)d_in[2];
    const float* W1  = (const float*)d_in[3];
    const float* b1  = (const float*)d_in[4];
    const float* W2  = (const float*)d_in[5];
    const float* b2  = (const float*)d_in[6];
    float* out = (float*)d_out;

    float *h0, *h1;
    cudaGetSymbolAddress((void**)&h0, g_h0);
    cudaGetSymbolAddress((void**)&h1, g_h1);

    dim3 blk(256);

    // K1: h0[b] = adj[b] @ x[b] + (1+eps)*x[b]
    gemm_epi<1><<<dim3(256 / BN, 4096 / BM, 8), blk>>>(
        adj, x, h0, x, eps, nullptr,
        /*N=*/256, /*K=*/4096,
        /*sA=*/4096LL * 4096, /*sB=*/4096LL * 256, /*sC=*/4096LL * 256);

    // K2: h1 = relu(h0 @ W1 + b1)   (M = 8*4096 = 32768 flattened)
    gemm_epi<2><<<dim3(512 / BN, 32768 / BM, 1), blk>>>(
        h0, W1, h1, nullptr, nullptr, b1,
        /*N=*/512, /*K=*/256, 0, 0, 0);

    // K3: out = h1 @ W2 + b2
    gemm_epi<3><<<dim3(256 / BN, 32768 / BM, 1), blk>>>(
        h1, W2, out, nullptr, nullptr, b2,
        /*N=*/256, /*K=*/512, 0, 0, 0);
}

// round 5
// speedup vs baseline: 4.2788x; 4.2788x over previous
#include <cuda_runtime.h>
#include <cuda_bf16.h>

// GIN MessagePassing — round 3: mma.sync (HMMA) bf16 hi/lo 3-pass GEMM.
// tcgen05 PTX is rejected at the harness's compute_103 virtual target, so we
// use the base-target tensor path: ldmatrix + mma.sync.m16n8k16.bf16 + cp.async.
//
//   pack:  x  -> [b][n=256][k=4096] bf16 hi/lo ;  W1 -> [512][256] ; W2 -> [256][512]
//   K1: h0[b] = adj[b]@x[b] + (1+eps)*x[b]   M=4096 N=256 K=4096 (x8)
//   K2: h1 = relu(h0@W1 + b1)                M=32768 N=512 K=256
//   K3: out = h1@W2 + b2                     M=32768 N=256 K=512
//
// CTA 128x256x32 double-buffered; 8 warps, warp tile 64x64;
// A fp32 -> bf16 hi/lo converted in-kernel; B pre-split via cp.async.
// D = Ahi*Bhi + Ahi*Blo + Alo*Bhi (fp32 accum).

#define BM 128
#define BN 256
#define BK 32
#define ASTR 80                      // padded row stride (32 bf16 = 64B + 16B skew)
#define A_TILE (128 * ASTR)          // 10240 B
#define B_TILE (256 * ASTR)          // 20480 B
#define OFF_ALO (A_TILE)
#define OFF_BHI (2 * A_TILE)
#define OFF_BLO (2 * A_TILE + B_TILE)
#define STAGE   (2 * A_TILE + 2 * B_TILE)   // 61440 B
#define SMEM_TOT (2 * STAGE)                // 122880 B

// ---------------- scratch (alloc-free rule: __device__ globals) ----------------
__device__ float g_h0[8u * 4096u * 256u];
__device__ float g_h1[8u * 4096u * 512u];
__device__ __align__(16) __nv_bfloat16 g_Bx_hi[8u * 256u * 4096u];
__device__ __align__(16) __nv_bfloat16 g_Bx_lo[8u * 256u * 4096u];
__device__ __align__(16) __nv_bfloat16 g_W1_hi[512u * 256u];
__device__ __align__(16) __nv_bfloat16 g_W1_lo[512u * 256u];
__device__ __align__(16) __nv_bfloat16 g_W2_hi[256u * 512u];
__device__ __align__(16) __nv_bfloat16 g_W2_lo[256u * 512u];

__device__ __forceinline__ unsigned s2u(const void* p) {
    unsigned a;
    asm("{ .reg .u64 t; cvta.to.shared.u64 t, %1; cvt.u32.u64 %0, t; }"
        : "=r"(a) : "l"(p));
    return a;
}
__device__ __forceinline__ void ldsm4(unsigned r[4], unsigned a) {
    asm volatile("ldmatrix.sync.aligned.m8n8.x4.shared.b16 {%0,%1,%2,%3}, [%4];"
                 : "=r"(r[0]), "=r"(r[1]), "=r"(r[2]), "=r"(r[3]) : "r"(a));
}
__device__ __forceinline__ void mma16816(float c[4], const unsigned a[4],
                                         const unsigned b[2]) {
    asm volatile(
        "mma.sync.aligned.m16n8k16.row.col.f32.bf16.bf16.f32 "
        "{%0,%1,%2,%3},{%4,%5,%6,%7},{%8,%9},{%0,%1,%2,%3};"
        : "+f"(c[0]), "+f"(c[1]), "+f"(c[2]), "+f"(c[3])
        : "r"(a[0]), "r"(a[1]), "r"(a[2]), "r"(a[3]), "r"(b[0]), "r"(b[1]));
}
__device__ __forceinline__ void cpa16(unsigned dst, const void* src) {
    asm volatile("cp.async.ca.shared.global [%0], [%1], 16;"
                 :: "r"(dst), "l"(src) : "memory");
}
__device__ __forceinline__ unsigned pack2bf(float x, float y) {
    const __nv_bfloat16 bx = __float2bfloat16(x), by = __float2bfloat16(y);
    return (unsigned)__bfloat16_as_ushort(bx) |
           ((unsigned)__bfloat16_as_ushort(by) << 16);
}

// ---------------- pack: [K,N] fp32 -> [N,K] bf16 hi/lo (batched) ----------------
__global__ __launch_bounds__(256)
void pack_bt(const float* __restrict__ in, __nv_bfloat16* __restrict__ ohi,
             __nv_bfloat16* __restrict__ olo, int K, int N)
{
    __shared__ float t[32][33];
    const int b = blockIdx.z;
    const float* ib = in + (long long)b * K * N;
    const int k0 = blockIdx.x * 32, n0 = blockIdx.y * 32;
    const int tx = threadIdx.x, ty = threadIdx.y;   // 32 x 8
#pragma unroll
    for (int i = 0; i < 4; ++i)
        t[ty + i * 8][tx] = ib[(long long)(k0 + ty + i * 8) * N + n0 + tx];
    __syncthreads();
    __nv_bfloat16* oh = ohi + (long long)b * K * N;
    __nv_bfloat16* ol = olo + (long long)b * K * N;
#pragma unroll
    for (int i = 0; i < 4; ++i) {
        const int n = n0 + ty + i * 8, k = k0 + tx;
        const float v = t[tx][ty + i * 8];
        const __nv_bfloat16 h = __float2bfloat16(v);
        const __nv_bfloat16 l = __float2bfloat16(v - __bfloat162float(h));
        oh[(long long)n * K + k] = h;
        ol[(long long)n * K + k] = l;
    }
}

// ---------------- HMMA GEMM ----------------
template<int EPI>
__global__ __launch_bounds__(256, 1)
void gemm_hmma(const float* __restrict__ A,
               const __nv_bfloat16* __restrict__ Bhi,
               const __nv_bfloat16* __restrict__ Blo,
               float* __restrict__ C,
               const float* __restrict__ xres,
               const float* __restrict__ epsp,
               const float* __restrict__ bias,
               int K, int ldC,
               long long sA, long long sB, long long sC)
{
    extern __shared__ char smem[];
    const int tid  = threadIdx.x;
    const int wid  = tid >> 5;
    const int lane = tid & 31;
    const int wm   = wid & 1;       // 2 warps in M
    const int wn   = wid >> 1;      // 4 warps in N
    const int bz   = blockIdx.z;
    const int n0   = blockIdx.x * BN;
    const long long row0 = (long long)blockIdx.y * BM;

    const float* Ap = A + (long long)bz * sA + row0 * K;
    const __nv_bfloat16* Bh = Bhi + (long long)bz * sB + (long long)n0 * K;
    const __nv_bfloat16* Bl = Blo + (long long)bz * sB + (long long)n0 * K;

    const unsigned sbase = s2u(smem);

    // ---- A prefetch registers (16 fp32 per thread per stage) ----
    const int ar = tid >> 1;                 // row 0..127
    const int ah = (tid & 1) * 16;           // first/second 16 columns
    float4 pa[4];
    auto ldA = [&](int k0) {
        const float* p = Ap + (long long)ar * K + k0 + ah;
        pa[0] = *(const float4*)(p);
        pa[1] = *(const float4*)(p + 4);
        pa[2] = *(const float4*)(p + 8);
        pa[3] = *(const float4*)(p + 12);
    };
    auto stA = [&](int s) {
        unsigned h[8], l[8];
#pragma unroll
        for (int q = 0; q < 4; ++q) {
            const float f[4] = {pa[q].x, pa[q].y, pa[q].z, pa[q].w};
            float r[4];
#pragma unroll
            for (int e = 0; e < 4; ++e)
                r[e] = f[e] - __bfloat162float(__float2bfloat16(f[e]));
            h[q * 2 + 0] = pack2bf(f[0], f[1]);
            h[q * 2 + 1] = pack2bf(f[2], f[3]);
            l[q * 2 + 0] = pack2bf(r[0], r[1]);
            l[q * 2 + 1] = pack2bf(r[2], r[3]);
        }
        char* base = smem + s * STAGE;
        const unsigned off = (unsigned)(ar * ASTR + ah * 2);
        *(uint4*)(base + off)                 = make_uint4(h[0], h[1], h[2], h[3]);
        *(uint4*)(base + off + 16)            = make_uint4(h[4], h[5], h[6], h[7]);
        *(uint4*)(base + OFF_ALO + off)       = make_uint4(l[0], l[1], l[2], l[3]);
        *(uint4*)(base + OFF_ALO + off + 16)  = make_uint4(l[4], l[5], l[6], l[7]);
    };
    // ---- B loader via cp.async ----
    const int bc = tid & 3;                  // 16B chunk in row
    const int bn = tid >> 2;                 // base row 0..63
    auto cpB = [&](int s, int k0) {
        const unsigned dhi = sbase + s * STAGE + OFF_BHI + bn * ASTR + bc * 16;
        const unsigned dlo = sbase + s * STAGE + OFF_BLO + bn * ASTR + bc * 16;
#pragma unroll
        for (int g = 0; g < 4; ++g) {
            const int n = bn + g * 64;
            const long long so = (long long)n * K + k0 + bc * 8;
            cpa16(dhi + g * 64 * ASTR, Bh + so);
            cpa16(dlo + g * 64 * ASTR, Bl + so);
        }
        asm volatile("cp.async.commit_group;" ::: "memory");
    };

    // ---- prologue ----
    ldA(0);
    cpB(0, 0);
    stA(0);
    asm volatile("cp.async.wait_group 0;" ::: "memory");
    __syncthreads();

    float acc[4][8][4];
#pragma unroll
    for (int i = 0; i < 4; ++i)
#pragma unroll
        for (int j = 0; j < 8; ++j)
#pragma unroll
            for (int e = 0; e < 4; ++e) acc[i][j][e] = 0.f;

    // ldmatrix per-lane base offsets
    const int lrow = lane & 7, quad = lane >> 3;
    const unsigned aoff =
        (unsigned)((wm * 64 + lrow + (quad & 1) * 8) * ASTR + ((quad >> 1) * 8) * 2);
    const unsigned boff =
        (unsigned)((wn * 64 + lrow + (quad >> 1) * 8) * ASTR + ((quad & 1) * 8) * 2);

    const int nIter = K / BK;
    for (int it = 0; it < nIter; ++it) {
        const int s = it & 1;
        const unsigned sb = sbase + s * STAGE;
        const bool more = (it + 1 < nIter);
        if (more) { ldA((it + 1) * BK); cpB(s ^ 1, (it + 1) * BK); }

#pragma unroll
        for (int k2 = 0; k2 < 2; ++k2) {
            const unsigned kb = (unsigned)(k2 * 32);   // 16 bf16 = 32 bytes
            unsigned a_hi[4][4], a_lo[4][4];
#pragma unroll
            for (int i = 0; i < 4; ++i) {
                ldsm4(a_hi[i], sb + aoff + i * 16 * ASTR + kb);
                ldsm4(a_lo[i], sb + OFF_ALO + aoff + i * 16 * ASTR + kb);
            }
#pragma unroll
            for (int p = 0; p < 4; ++p) {   // pairs of n-tiles
                unsigned b_hi[4], b_lo[4];
                ldsm4(b_hi, sb + OFF_BHI + boff + p * 16 * ASTR + kb);
                ldsm4(b_lo, sb + OFF_BLO + boff + p * 16 * ASTR + kb);
#pragma unroll
                for (int i = 0; i < 4; ++i) {
                    mma16816(acc[i][2 * p + 0], a_hi[i], b_hi + 0);
                    mma16816(acc[i][2 * p + 1], a_hi[i], b_hi + 2);
                    mma16816(acc[i][2 * p + 0], a_hi[i], b_lo + 0);
                    mma16816(acc[i][2 * p + 1], a_hi[i], b_lo + 2);
                    mma16816(acc[i][2 * p + 0], a_lo[i], b_hi + 0);
                    mma16816(acc[i][2 * p + 1], a_lo[i], b_hi + 2);
                }
            }
        }
        if (more) {
            stA(s ^ 1);
            asm volatile("cp.async.wait_group 0;" ::: "memory");
        }
        __syncthreads();
    }

    // ---- epilogue ----
    const int r4 = lane >> 2, c2 = (lane & 3) * 2;
    float epsv = 0.f;
    if (EPI == 1) epsv = 1.0f + epsp[0];
    float* Cb = C + (long long)bz * sC;
    const float* Xb = (EPI == 1) ? (xres + (long long)bz * sC) : nullptr;

#pragma unroll
    for (int i = 0; i < 4; ++i) {
        const long long rg0 = row0 + wm * 64 + i * 16 + r4;
#pragma unroll
        for (int j = 0; j < 8; ++j) {
            const int cg = n0 + wn * 64 + j * 8 + c2;
            float2 v0 = make_float2(acc[i][j][0], acc[i][j][1]);
            float2 v1 = make_float2(acc[i][j][2], acc[i][j][3]);
            if (EPI == 1) {
                const float2 x0 = *(const float2*)(Xb + rg0 * ldC + cg);
                const float2 x1 = *(const float2*)(Xb + (rg0 + 8) * ldC + cg);
                v0.x = fmaf(epsv, x0.x, v0.x); v0.y = fmaf(epsv, x0.y, v0.y);
                v1.x = fmaf(epsv, x1.x, v1.x); v1.y = fmaf(epsv, x1.y, v1.y);
            } else if (EPI == 2) {
                const float bx = bias[cg], by = bias[cg + 1];
                v0.x = fmaxf(v0.x + bx, 0.f); v0.y = fmaxf(v0.y + by, 0.f);
                v1.x = fmaxf(v1.x + bx, 0.f); v1.y = fmaxf(v1.y + by, 0.f);
            } else {
                const float bx = bias[cg], by = bias[cg + 1];
                v0.x += bx; v0.y += by;
                v1.x += bx; v1.y += by;
            }
            *(float2*)(Cb + rg0 * ldC + cg)       = v0;
            *(float2*)(Cb + (rg0 + 8) * ldC + cg) = v1;
        }
    }
}

extern "C" void kernel_launch(void* const* d_in, const int* in_sizes, int n_in,
                              void* d_out, int out_size)
{
    (void)in_sizes; (void)n_in; (void)out_size;
    const float* x   = (const float*)d_in[0];
    const float* adj = (const float*)d_in[1];
    const float* eps = (const float*)d_in[2];
    const float* W1  = (const float*)d_in[3];
    const float* b1  = (const float*)d_in[4];
    const float* W2  = (const float*)d_in[5];
    const float* b2  = (const float*)d_in[6];
    float* out = (float*)d_out;

    float *h0, *h1;
    __nv_bfloat16 *bxh, *bxl, *w1h, *w1l, *w2h, *w2l;
    cudaGetSymbolAddress((void**)&h0,  g_h0);
    cudaGetSymbolAddress((void**)&h1,  g_h1);
    cudaGetSymbolAddress((void**)&bxh, g_Bx_hi);
    cudaGetSymbolAddress((void**)&bxl, g_Bx_lo);
    cudaGetSymbolAddress((void**)&w1h, g_W1_hi);
    cudaGetSymbolAddress((void**)&w1l, g_W1_lo);
    cudaGetSymbolAddress((void**)&w2h, g_W2_hi);
    cudaGetSymbolAddress((void**)&w2l, g_W2_lo);

    cudaFuncSetAttribute(gemm_hmma<1>, cudaFuncAttributeMaxDynamicSharedMemorySize, SMEM_TOT);
    cudaFuncSetAttribute(gemm_hmma<2>, cudaFuncAttributeMaxDynamicSharedMemorySize, SMEM_TOT);
    cudaFuncSetAttribute(gemm_hmma<3>, cudaFuncAttributeMaxDynamicSharedMemorySize, SMEM_TOT);

    const dim3 tb(32, 8);
    pack_bt<<<dim3(128, 8, 8), tb>>>(x,  bxh, bxl, 4096, 256);
    pack_bt<<<dim3(8, 16, 1),  tb>>>(W1, w1h, w1l, 256, 512);
    pack_bt<<<dim3(16, 8, 1),  tb>>>(W2, w2h, w2l, 512, 256);

    // K1: h0 = adj@x + (1+eps)*x    grid (N/BN=1, M/BM=32, 8)
    gemm_hmma<1><<<dim3(1, 32, 8), 256, SMEM_TOT>>>(
        adj, bxh, bxl, h0, x, eps, nullptr,
        /*K=*/4096, /*ldC=*/256,
        4096LL * 4096, 256LL * 4096, 4096LL * 256);

    // K2: h1 = relu(h0@W1 + b1)     grid (512/256=2, 32768/128=256)
    gemm_hmma<2><<<dim3(2, 256, 1), 256, SMEM_TOT>>>(
        h0, w1h, w1l, h1, nullptr, nullptr, b1,
        /*K=*/256, /*ldC=*/512, 0, 0, 0);

    // K3: out = h1@W2 + b2          grid (1, 256)
    gemm_hmma<3><<<dim3(1, 256, 1), 256, SMEM_TOT>>>(
        h1, w2h, w2l, out, nullptr, nullptr, b2,
        /*K=*/512, /*ldC=*/256, 0, 0, 0);
}